// round 2
// baseline (speedup 1.0000x reference)
#include <cuda_runtime.h>
#include <cuda_bf16.h>
#include <cstdint>

// ---------------- problem constants ----------------
#define NMAX   50000
#define EMAX   800000
#define ETMAX  (EMAX + NMAX)
#define F      256            // feature width of every stage (H*C = 256)

// ---------------- scratch (static device arrays; no allocation) ----------------
__device__ float g_xl[(size_t)NMAX * F];
__device__ float g_xr[(size_t)NMAX * F];
__device__ float g_agg[(size_t)NMAX * F];
__device__ float g_h[(size_t)NMAX * F];
__device__ float g_logits[(size_t)ETMAX * 4];
__device__ float g_mx[(size_t)NMAX * 4];
__device__ float g_dn[(size_t)NMAX * 4];
__device__ int   g_mode;   // 1 = edge_index is int64, 0 = int32

// ---------------- edge dtype detection ----------------
// Interpret buffer as int64; if all sampled values are valid node ids, it is
// int64. An int32 buffer read as int64 yields lo + hi*2^32 with hi = next edge
// id (almost surely nonzero) -> out of range -> mode 0.
__global__ void detect_mode(const void* ei, int n_elems, int N) {
    const long long* p = (const long long*)ei;
    int lim = n_elems < 4096 ? n_elems : 4096;
    int ok = 1;
    for (int i = 0; i < lim; i++) {
        long long v = p[i];
        if (v < 0 || v >= (long long)N) { ok = 0; break; }
    }
    g_mode = ok;
}

__device__ __forceinline__ void load_edge(const void* ei, int mode, int E, int N,
                                          int w, long long& s, long long& d) {
    if (w >= E) { s = d = (long long)(w - E); return; }   // self-loop
    if (mode) {
        const long long* p = (const long long*)ei;
        s = p[w]; d = p[E + w];
    } else {
        const int* p = (const int*)ei;
        s = p[w]; d = p[E + w];
    }
}

// ---------------- helpers ----------------
__device__ __forceinline__ void atomicMaxF(float* addr, float v) {
    if (v >= 0.f) atomicMax((int*)addr, __float_as_int(v));
    else          atomicMin((unsigned int*)addr, __float_as_uint(v));
}

// ---------------- GEMM: C[M,256] = A[M,256] * B[256,256] ----------------
__global__ void __launch_bounds__(256) gemm256(
    const float* __restrict__ A, const float* __restrict__ B,
    float* __restrict__ C, int M)
{
    __shared__ float As[16][64];   // [k][m]
    __shared__ float Bs[16][64];   // [k][n]

    const int tid = threadIdx.x;
    const int bm = blockIdx.x * 64;
    const int bn = blockIdx.y * 64;
    const int tx = tid & 15;
    const int ty = tid >> 4;

    const int arow = tid >> 2;
    const int akq  = tid & 3;
    const int brow = tid >> 4;
    const int bc4  = tid & 15;

    float acc[4][4];
#pragma unroll
    for (int i = 0; i < 4; i++)
#pragma unroll
        for (int j = 0; j < 4; j++) acc[i][j] = 0.f;

    for (int k0 = 0; k0 < 256; k0 += 16) {
        float4 av;
        if (bm + arow < M)
            av = *(const float4*)(A + (size_t)(bm + arow) * F + k0 + akq * 4);
        else
            av = make_float4(0.f, 0.f, 0.f, 0.f);
        float4 bv = *(const float4*)(B + (size_t)(k0 + brow) * F + bn + bc4 * 4);

        __syncthreads();
        As[akq * 4 + 0][arow] = av.x;
        As[akq * 4 + 1][arow] = av.y;
        As[akq * 4 + 2][arow] = av.z;
        As[akq * 4 + 3][arow] = av.w;
        *(float4*)&Bs[brow][bc4 * 4] = bv;
        __syncthreads();

#pragma unroll
        for (int k = 0; k < 16; k++) {
            float4 a4 = *(const float4*)&As[k][ty * 4];
            float4 b4 = *(const float4*)&Bs[k][tx * 4];
            float a[4] = {a4.x, a4.y, a4.z, a4.w};
            float b[4] = {b4.x, b4.y, b4.z, b4.w};
#pragma unroll
            for (int i = 0; i < 4; i++)
#pragma unroll
                for (int j = 0; j < 4; j++) acc[i][j] += a[i] * b[j];
        }
    }

#pragma unroll
    for (int i = 0; i < 4; i++) {
        int r = bm + ty * 4 + i;
        if (r < M) {
            float4 v = make_float4(acc[i][0], acc[i][1], acc[i][2], acc[i][3]);
            *(float4*)(C + (size_t)r * F + bn + tx * 4) = v;
        }
    }
}

// ---------------- per-layer init ----------------
__global__ void init_layer(float* __restrict__ agg, float* __restrict__ mx,
                           float* __restrict__ dn, int n_agg, int n_mh)
{
    int i = blockIdx.x * blockDim.x + threadIdx.x;
    if (i < n_agg) agg[i] = 0.f;
    if (i < n_mh) { mx[i] = __int_as_float(0xFF800000); dn[i] = 0.f; }
}

// ---------------- edge pass 1: logits + segment max ----------------
template <int H, int C>
__global__ void __launch_bounds__(256) edge_logits(
    const void* __restrict__ ei, int E, int N,
    const float* __restrict__ xl, const float* __restrict__ xr,
    const float* __restrict__ att,
    float* __restrict__ logits, float* __restrict__ mx)
{
    int w = (blockIdx.x * blockDim.x + threadIdx.x) >> 5;
    int lane = threadIdx.x & 31;
    int ET = E + N;
    if (w >= ET) return;
    int mode = g_mode;
    long long s, d;
    load_edge(ei, mode, E, N, w, s, d);

    const float4* xls = (const float4*)(xl + (size_t)s * F);
    const float4* xrd = (const float4*)(xr + (size_t)d * F);
    const float4* a4  = (const float4*)att;

    float part[2];
#pragma unroll
    for (int j = 0; j < 2; j++) {
        int i4 = lane + 32 * j;
        float4 l = xls[i4];
        float4 r = xrd[i4];
        float4 a = a4[i4];
        float vx = l.x + r.x; vx = vx > 0.f ? vx : 0.2f * vx;
        float vy = l.y + r.y; vy = vy > 0.f ? vy : 0.2f * vy;
        float vz = l.z + r.z; vz = vz > 0.f ? vz : 0.2f * vz;
        float vw = l.w + r.w; vw = vw > 0.f ? vw : 0.2f * vw;
        part[j] = vx * a.x + vy * a.y + vz * a.z + vw * a.w;
    }

    if constexpr (H == 1) {
        float sum = part[0] + part[1];
#pragma unroll
        for (int o = 16; o; o >>= 1) sum += __shfl_xor_sync(0xffffffffu, sum, o);
        if (lane == 0) {
            logits[w] = sum;
            atomicMaxF(&mx[d], sum);
        }
    } else {  // H==4, C==64
#pragma unroll
        for (int o = 8; o; o >>= 1) {
            part[0] += __shfl_xor_sync(0xffffffffu, part[0], o);
            part[1] += __shfl_xor_sync(0xffffffffu, part[1], o);
        }
        if ((lane & 15) == 0) {
            int h0 = lane >> 4;
            logits[(size_t)w * 4 + h0]     = part[0];
            logits[(size_t)w * 4 + h0 + 2] = part[1];
            atomicMaxF(&mx[d * 4 + h0],     part[0]);
            atomicMaxF(&mx[d * 4 + h0 + 2], part[1]);
        }
    }
}

// ---------------- edge pass 2: softmax denominator ----------------
template <int H>
__global__ void __launch_bounds__(256) edge_denom(
    const void* __restrict__ ei, int E, int N,
    const float* __restrict__ logits, const float* __restrict__ mx,
    float* __restrict__ dn)
{
    int e = blockIdx.x * blockDim.x + threadIdx.x;
    int ET = E + N;
    if (e >= ET) return;
    int mode = g_mode;
    long long s, d;
    load_edge(ei, mode, E, N, e, s, d);
#pragma unroll
    for (int h = 0; h < H; h++) {
        float ex = __expf(logits[(size_t)e * H + h] - mx[d * H + h]);
        atomicAdd(&dn[d * H + h], ex);
    }
}

// ---------------- edge pass 3: weighted aggregation ----------------
template <int H, int C>
__global__ void __launch_bounds__(256) edge_agg(
    const void* __restrict__ ei, int E, int N,
    const float* __restrict__ xl,
    const float* __restrict__ logits, const float* __restrict__ mx,
    const float* __restrict__ dn, float* __restrict__ agg)
{
    int w = (blockIdx.x * blockDim.x + threadIdx.x) >> 5;
    int lane = threadIdx.x & 31;
    int ET = E + N;
    if (w >= ET) return;
    int mode = g_mode;
    long long s, d;
    load_edge(ei, mode, E, N, w, s, d);

    const float4* xls = (const float4*)(xl + (size_t)s * F);
    float* out = agg + (size_t)d * F;

#pragma unroll
    for (int j = 0; j < 2; j++) {
        int i4 = lane + 32 * j;
        int h  = i4 / (C / 4);
        float a = __expf(logits[(size_t)w * H + h] - mx[d * H + h]) / dn[d * H + h];
        float4 v = xls[i4];
        atomicAdd(out + i4 * 4 + 0, a * v.x);
        atomicAdd(out + i4 * 4 + 1, a * v.y);
        atomicAdd(out + i4 * 4 + 2, a * v.z);
        atomicAdd(out + i4 * 4 + 3, a * v.w);
    }
}

// ---------------- epilogues ----------------
__global__ void finish_elu(const float* __restrict__ agg, const float* __restrict__ b,
                           float* __restrict__ out, int n)
{
    int i = blockIdx.x * blockDim.x + threadIdx.x;
    if (i >= n) return;
    float v = agg[i] + b[i & (F - 1)];
    out[i] = v > 0.f ? v : (__expf(v) - 1.f);
}

__global__ void finish_bias(const float* __restrict__ agg, const float* __restrict__ b,
                            float* __restrict__ out, int n)
{
    int i = blockIdx.x * blockDim.x + threadIdx.x;
    if (i >= n) return;
    out[i] = agg[i] + b[i & (F - 1)];
}

// ---------------- host ----------------
extern "C" void kernel_launch(void* const* d_in, const int* in_sizes, int n_in,
                              void* d_out, int out_size)
{
    const float* x    = (const float*)d_in[0];
    const void*  ei   = d_in[1];
    const float* Wl1  = (const float*)d_in[2];
    const float* Wr1  = (const float*)d_in[3];
    const float* att1 = (const float*)d_in[4];
    const float* b1   = (const float*)d_in[5];
    const float* Wl2  = (const float*)d_in[6];
    const float* Wr2  = (const float*)d_in[7];
    const float* att2 = (const float*)d_in[8];
    const float* b2   = (const float*)d_in[9];
    float* out = (float*)d_out;

    int N  = in_sizes[0] / F;
    int E  = in_sizes[1] / 2;
    int ET = E + N;

    float *xl, *xr, *agg, *hb, *lg, *mx, *dn;
    cudaGetSymbolAddress((void**)&xl,  g_xl);
    cudaGetSymbolAddress((void**)&xr,  g_xr);
    cudaGetSymbolAddress((void**)&agg, g_agg);
    cudaGetSymbolAddress((void**)&hb,  g_h);
    cudaGetSymbolAddress((void**)&lg,  g_logits);
    cudaGetSymbolAddress((void**)&mx,  g_mx);
    cudaGetSymbolAddress((void**)&dn,  g_dn);

    dim3 gg((N + 63) / 64, 4);
    int nagg = N * F;
    int nb   = (nagg + 255) / 256;
    int eb   = (ET * 32 + 255) / 256;   // warp per edge
    int ebt  = (ET + 255) / 256;        // thread per edge

    detect_mode<<<1, 1>>>(ei, in_sizes[1], N);

    // ---- layer 1 (H=4, C=64) ----
    gemm256<<<gg, 256>>>(x, Wl1, xl, N);
    gemm256<<<gg, 256>>>(x, Wr1, xr, N);
    init_layer<<<nb, 256>>>(agg, mx, dn, nagg, N * 4);
    edge_logits<4, 64><<<eb, 256>>>(ei, E, N, xl, xr, att1, lg, mx);
    edge_denom<4><<<ebt, 256>>>(ei, E, N, lg, mx, dn);
    edge_agg<4, 64><<<eb, 256>>>(ei, E, N, xl, lg, mx, dn, agg);
    finish_elu<<<nb, 256>>>(agg, b1, hb, nagg);

    // ---- layer 2 (H=1, C=256) ----
    gemm256<<<gg, 256>>>(hb, Wl2, xl, N);
    gemm256<<<gg, 256>>>(hb, Wr2, xr, N);
    init_layer<<<nb, 256>>>(agg, mx, dn, nagg, N * 1);
    edge_logits<1, 256><<<eb, 256>>>(ei, E, N, xl, xr, att2, lg, mx);
    edge_denom<1><<<ebt, 256>>>(ei, E, N, lg, mx, dn);
    edge_agg<1, 256><<<eb, 256>>>(ei, E, N, xl, lg, mx, dn, agg);
    finish_bias<<<nb, 256>>>(agg, b2, out, nagg);
}

// round 3
// speedup vs baseline: 1.9751x; 1.9751x over previous
#include <cuda_runtime.h>
#include <cuda_bf16.h>
#include <cstdint>

// ---------------- problem constants ----------------
#define NMAX   50000
#define EMAX   800000
#define ETMAX  (EMAX + NMAX)
#define F      256            // feature width of every stage (H*C = 256)

// ---------------- scratch (static device arrays; no allocation) ----------------
__device__ float g_xl[(size_t)NMAX * F];
__device__ float g_xr[(size_t)NMAX * F];
__device__ float g_h [(size_t)NMAX * F];
__device__ float g_logits[(size_t)ETMAX * 4];
__device__ float g_mx[(size_t)NMAX * 4];
__device__ float g_dn[(size_t)NMAX * 4];
__device__ int   g_deg[NMAX];
__device__ int   g_cur[NMAX];
__device__ int   g_row[NMAX + 1];
__device__ int   g_src[ETMAX];
__device__ int   g_mode;   // 1 = edge_index is int64, 0 = int32

// ---------------- edge dtype detection ----------------
__global__ void detect_mode(const void* ei, int n_elems, int N) {
    const long long* p = (const long long*)ei;
    int lim = n_elems < 4096 ? n_elems : 4096;
    int ok = 1;
    for (int i = 0; i < lim; i++) {
        long long v = p[i];
        if (v < 0 || v >= (long long)N) { ok = 0; break; }
    }
    g_mode = ok;
}

__device__ __forceinline__ void load_edge(const void* ei, int mode, int E, int N,
                                          int w, int& s, int& d) {
    if (w >= E) { s = d = w - E; return; }   // self-loop
    if (mode) {
        const long long* p = (const long long*)ei;
        s = (int)p[w]; d = (int)p[E + w];
    } else {
        const int* p = (const int*)ei;
        s = p[w]; d = p[E + w];
    }
}

// ---------------- CSR build ----------------
__global__ void zero_counts(int N) {
    int i = blockIdx.x * blockDim.x + threadIdx.x;
    if (i < N) { g_deg[i] = 0; g_cur[i] = 0; }
}

__global__ void count_deg(const void* __restrict__ ei, int E, int N) {
    int e = blockIdx.x * blockDim.x + threadIdx.x;
    if (e >= E + N) return;
    int s, d; load_edge(ei, g_mode, E, N, e, s, d);
    atomicAdd(&g_deg[d], 1);
}

__global__ void scan_deg(int N) {
    __shared__ int sums[1024];
    int tid = threadIdx.x;
    int chunk = (N + 1023) >> 10;
    int s0 = tid * chunk;
    int s1 = s0 + chunk < N ? s0 + chunk : N;
    int s = 0;
    for (int i = s0; i < s1; i++) s += g_deg[i];
    sums[tid] = s;
    __syncthreads();
    for (int off = 1; off < 1024; off <<= 1) {
        int v = (tid >= off) ? sums[tid - off] : 0;
        __syncthreads();
        sums[tid] += v;
        __syncthreads();
    }
    int base = tid ? sums[tid - 1] : 0;   // exclusive prefix
    for (int i = s0; i < s1; i++) { g_row[i] = base; base += g_deg[i]; }
    if (tid == 1023) g_row[N] = sums[1023];
}

__global__ void scatter_edges(const void* __restrict__ ei, int E, int N) {
    int e = blockIdx.x * blockDim.x + threadIdx.x;
    if (e >= E + N) return;
    int s, d; load_edge(ei, g_mode, E, N, e, s, d);
    int pos = g_row[d] + atomicAdd(&g_cur[d], 1);
    g_src[pos] = s;
}

// ---------------- GEMM: C[M,256] = A[M,256] * B[256,256] ----------------
// 128x128 tile, 256 threads, 8x8 microtile, packed fma.rn.f32x2.
// A duplicated in smem ({a,a} pairs -> broadcast LDS), B split into two
// 16B-stride regions for conflict-free LDS.128 pair loads.
#define FMA2(acc, a, b) \
    asm("fma.rn.f32x2 %0, %1, %2, %0;" : "+l"(acc) : "l"(a), "l"(b))

__device__ __forceinline__ float2 ull2f2(unsigned long long u) {
    float2 f;
    asm("mov.b64 {%0, %1}, %2;" : "=f"(f.x), "=f"(f.y) : "l"(u));
    return f;
}

__global__ void __launch_bounds__(256, 2) gemm256x2(
    const float* __restrict__ A, const float* __restrict__ B,
    float* __restrict__ C, int M)
{
    __shared__ float As2[16][256];   // [k][2m], each a duplicated
    __shared__ float BsA[16][64];    // cols with (c&7)<4, packed at (c>>3)*4+(c&3)
    __shared__ float BsB[16][64];    // cols with (c&7)>=4

    const int tid = threadIdx.x;
    const int bm = blockIdx.x * 128;
    const int bn = blockIdx.y * 128;
    const int tx = tid & 15;
    const int ty = tid >> 4;

    const int arow = tid >> 1;        // 0..127
    const int aq0  = (tid & 1) * 2;   // first of two float4 slots along k
    const int brow = tid >> 4;        // 0..15
    const int bc8  = tid & 15;        // col octet

    unsigned long long acc[8][4] = {};

    float4 a0, a1, b0, b1;
    {
        const float* ab = A + (size_t)(bm + arow) * F;
        if (bm + arow < M) {
            a0 = *(const float4*)(ab + aq0 * 4);
            a1 = *(const float4*)(ab + aq0 * 4 + 4);
        } else { a0 = a1 = make_float4(0.f,0.f,0.f,0.f); }
        const float* bb = B + (size_t)brow * F + bn + bc8 * 8;
        b0 = *(const float4*)bb;
        b1 = *(const float4*)(bb + 4);
    }

    for (int k0 = 0;;) {
        __syncthreads();
        {
            const float* av0 = &a0.x;
            const float* av1 = &a1.x;
#pragma unroll
            for (int t = 0; t < 4; t++) {
                int k  = aq0 * 4 + t;
                As2[k][2 * arow] = av0[t];  As2[k][2 * arow + 1] = av0[t];
                int k2 = aq0 * 4 + 4 + t;
                As2[k2][2 * arow] = av1[t]; As2[k2][2 * arow + 1] = av1[t];
            }
            *(float4*)&BsA[brow][bc8 * 4] = b0;
            *(float4*)&BsB[brow][bc8 * 4] = b1;
        }
        __syncthreads();

        k0 += 16;
        bool last = (k0 >= 256);
        if (!last) {
            const float* ab = A + (size_t)(bm + arow) * F + k0;
            if (bm + arow < M) {
                a0 = *(const float4*)(ab + aq0 * 4);
                a1 = *(const float4*)(ab + aq0 * 4 + 4);
            } else { a0 = a1 = make_float4(0.f,0.f,0.f,0.f); }
            const float* bb = B + (size_t)(k0 + brow) * F + bn + bc8 * 8;
            b0 = *(const float4*)bb;
            b1 = *(const float4*)(bb + 4);
        }

#pragma unroll
        for (int k = 0; k < 16; k++) {
            ulonglong2 adx = *(const ulonglong2*)&As2[k][ty * 16];
            ulonglong2 ady = *(const ulonglong2*)&As2[k][ty * 16 + 4];
            ulonglong2 adz = *(const ulonglong2*)&As2[k][ty * 16 + 8];
            ulonglong2 adw = *(const ulonglong2*)&As2[k][ty * 16 + 12];
            ulonglong2 bpA = *(const ulonglong2*)&BsA[k][tx * 4];
            ulonglong2 bpB = *(const ulonglong2*)&BsB[k][tx * 4];
            unsigned long long ad[8] = {adx.x, adx.y, ady.x, ady.y,
                                        adz.x, adz.y, adw.x, adw.y};
            unsigned long long bp[4] = {bpA.x, bpA.y, bpB.x, bpB.y};
#pragma unroll
            for (int i = 0; i < 8; i++)
#pragma unroll
                for (int jp = 0; jp < 4; jp++)
                    FMA2(acc[i][jp], ad[i], bp[jp]);
        }
        if (last) break;
    }

#pragma unroll
    for (int i = 0; i < 8; i++) {
        int r = bm + ty * 8 + i;
        if (r < M) {
            float2 c0 = ull2f2(acc[i][0]);
            float2 c1 = ull2f2(acc[i][1]);
            float2 c2 = ull2f2(acc[i][2]);
            float2 c3 = ull2f2(acc[i][3]);
            float* cp = C + (size_t)r * F + bn + tx * 8;
            *(float4*)cp       = make_float4(c0.x, c0.y, c1.x, c1.y);
            *(float4*)(cp + 4) = make_float4(c2.x, c2.y, c3.x, c3.y);
        }
    }
}

// ---------------- pass A: per-dst logits + max + denom (warp per dst) ----------------
template <int H>
__global__ void __launch_bounds__(256) dst_logits(
    const float* __restrict__ xl, const float* __restrict__ xr,
    const float* __restrict__ att, int N)
{
    int w = (blockIdx.x * blockDim.x + threadIdx.x) >> 5;
    int lane = threadIdx.x & 31;
    if (w >= N) return;

    const float4* xr4 = (const float4*)(xr + (size_t)w * F);
    float4 r0 = xr4[lane], r1 = xr4[lane + 32];
    const float4* a4 = (const float4*)att;
    float4 a0 = a4[lane], a1 = a4[lane + 32];

    int row0 = g_row[w], row1 = g_row[w + 1];
    const float NEG_INF = __int_as_float(0xFF800000);
    float m0 = NEG_INF, m1 = NEG_INF;

    for (int i = row0; i < row1; i++) {
        int s = g_src[i];
        const float4* xl4 = (const float4*)(xl + (size_t)s * F);
        float4 l0 = xl4[lane], l1 = xl4[lane + 32];

        float vx = l0.x + r0.x; vx = vx > 0.f ? vx : 0.2f * vx;
        float vy = l0.y + r0.y; vy = vy > 0.f ? vy : 0.2f * vy;
        float vz = l0.z + r0.z; vz = vz > 0.f ? vz : 0.2f * vz;
        float vw = l0.w + r0.w; vw = vw > 0.f ? vw : 0.2f * vw;
        float p0 = vx * a0.x + vy * a0.y + vz * a0.z + vw * a0.w;

        vx = l1.x + r1.x; vx = vx > 0.f ? vx : 0.2f * vx;
        vy = l1.y + r1.y; vy = vy > 0.f ? vy : 0.2f * vy;
        vz = l1.z + r1.z; vz = vz > 0.f ? vz : 0.2f * vz;
        vw = l1.w + r1.w; vw = vw > 0.f ? vw : 0.2f * vw;
        float p1 = vx * a1.x + vy * a1.y + vz * a1.z + vw * a1.w;

        if (H == 1) {
            float sum = p0 + p1;
#pragma unroll
            for (int o = 16; o; o >>= 1) sum += __shfl_xor_sync(0xffffffffu, sum, o);
            if (lane == 0) {
                g_logits[i] = sum;
                m0 = fmaxf(m0, sum);
            }
        } else {
#pragma unroll
            for (int o = 8; o; o >>= 1) {
                p0 += __shfl_xor_sync(0xffffffffu, p0, o);
                p1 += __shfl_xor_sync(0xffffffffu, p1, o);
            }
            if ((lane & 15) == 0) {
                int h0 = lane >> 4;
                g_logits[(size_t)i * 4 + h0]     = p0;
                g_logits[(size_t)i * 4 + h0 + 2] = p1;
                m0 = fmaxf(m0, p0);
                m1 = fmaxf(m1, p1);
            }
        }
    }

    if (H == 1) {
        float mx = __shfl_sync(0xffffffffu, m0, 0);
        float dn = 0.f;
        for (int i = row0 + lane; i < row1; i += 32)
            dn += __expf(g_logits[i] - mx);
#pragma unroll
        for (int o = 16; o; o >>= 1) dn += __shfl_xor_sync(0xffffffffu, dn, o);
        if (lane == 0) { g_mx[w] = mx; g_dn[w] = dn; }
    } else {
        float mh0 = __shfl_sync(0xffffffffu, m0, 0);
        float mh1 = __shfl_sync(0xffffffffu, m0, 16);
        float mh2 = __shfl_sync(0xffffffffu, m1, 0);
        float mh3 = __shfl_sync(0xffffffffu, m1, 16);
        float d0 = 0.f, d1 = 0.f, d2 = 0.f, d3 = 0.f;
        for (int i = row0 + lane; i < row1; i += 32) {
            float4 lg = *(const float4*)&g_logits[(size_t)i * 4];
            d0 += __expf(lg.x - mh0);
            d1 += __expf(lg.y - mh1);
            d2 += __expf(lg.z - mh2);
            d3 += __expf(lg.w - mh3);
        }
#pragma unroll
        for (int o = 16; o; o >>= 1) {
            d0 += __shfl_xor_sync(0xffffffffu, d0, o);
            d1 += __shfl_xor_sync(0xffffffffu, d1, o);
            d2 += __shfl_xor_sync(0xffffffffu, d2, o);
            d3 += __shfl_xor_sync(0xffffffffu, d3, o);
        }
        if (lane == 0) {
            *(float4*)&g_mx[(size_t)w * 4] = make_float4(mh0, mh1, mh2, mh3);
            *(float4*)&g_dn[(size_t)w * 4] = make_float4(d0, d1, d2, d3);
        }
    }
}

// ---------------- pass B: per-dst aggregation + bias + activation ----------------
// MODE 0: ELU (layer 1), MODE 1: bias only (layer 2)
template <int H, int MODE>
__global__ void __launch_bounds__(256) dst_agg(
    const float* __restrict__ xl, const float* __restrict__ bias,
    float* __restrict__ out, int N)
{
    int w = (blockIdx.x * blockDim.x + threadIdx.x) >> 5;
    int lane = threadIdx.x & 31;
    if (w >= N) return;

    int row0 = g_row[w], row1 = g_row[w + 1];
    float4 acc0 = make_float4(0.f,0.f,0.f,0.f);
    float4 acc1 = make_float4(0.f,0.f,0.f,0.f);

    if (H == 1) {
        float mx  = g_mx[w];
        float idn = 1.f / g_dn[w];
        for (int i = row0; i < row1; i++) {
            int s = g_src[i];
            float al = __expf(g_logits[i] - mx) * idn;
            const float4* xl4 = (const float4*)(xl + (size_t)s * F);
            float4 l0 = xl4[lane], l1 = xl4[lane + 32];
            acc0.x += al * l0.x; acc0.y += al * l0.y;
            acc0.z += al * l0.z; acc0.w += al * l0.w;
            acc1.x += al * l1.x; acc1.y += al * l1.y;
            acc1.z += al * l1.z; acc1.w += al * l1.w;
        }
    } else {
        float4 mx4 = *(const float4*)&g_mx[(size_t)w * 4];
        float4 dn4 = *(const float4*)&g_dn[(size_t)w * 4];
        int hA = lane >> 4;              // head for acc0: 0 or 1
        float mxA = hA ? mx4.y : mx4.x;
        float mxB = hA ? mx4.w : mx4.z;  // head hA+2 for acc1
        float idA = 1.f / (hA ? dn4.y : dn4.x);
        float idB = 1.f / (hA ? dn4.w : dn4.z);
        for (int i = row0; i < row1; i++) {
            int s = g_src[i];
            float4 lg = *(const float4*)&g_logits[(size_t)i * 4];
            float la = __expf((hA ? lg.y : lg.x) - mxA) * idA;
            float lb = __expf((hA ? lg.w : lg.z) - mxB) * idB;
            const float4* xl4 = (const float4*)(xl + (size_t)s * F);
            float4 l0 = xl4[lane], l1 = xl4[lane + 32];
            acc0.x += la * l0.x; acc0.y += la * l0.y;
            acc0.z += la * l0.z; acc0.w += la * l0.w;
            acc1.x += lb * l1.x; acc1.y += lb * l1.y;
            acc1.z += lb * l1.z; acc1.w += lb * l1.w;
        }
    }

    const float4* b4 = (const float4*)bias;
    float4 b0 = b4[lane], b1 = b4[lane + 32];
    acc0.x += b0.x; acc0.y += b0.y; acc0.z += b0.z; acc0.w += b0.w;
    acc1.x += b1.x; acc1.y += b1.y; acc1.z += b1.z; acc1.w += b1.w;

    if (MODE == 0) {   // ELU
        acc0.x = acc0.x > 0.f ? acc0.x : (__expf(acc0.x) - 1.f);
        acc0.y = acc0.y > 0.f ? acc0.y : (__expf(acc0.y) - 1.f);
        acc0.z = acc0.z > 0.f ? acc0.z : (__expf(acc0.z) - 1.f);
        acc0.w = acc0.w > 0.f ? acc0.w : (__expf(acc0.w) - 1.f);
        acc1.x = acc1.x > 0.f ? acc1.x : (__expf(acc1.x) - 1.f);
        acc1.y = acc1.y > 0.f ? acc1.y : (__expf(acc1.y) - 1.f);
        acc1.z = acc1.z > 0.f ? acc1.z : (__expf(acc1.z) - 1.f);
        acc1.w = acc1.w > 0.f ? acc1.w : (__expf(acc1.w) - 1.f);
    }

    float4* o4 = (float4*)(out + (size_t)w * F);
    o4[lane]      = acc0;
    o4[lane + 32] = acc1;
}

// ---------------- host ----------------
extern "C" void kernel_launch(void* const* d_in, const int* in_sizes, int n_in,
                              void* d_out, int out_size)
{
    const float* x    = (const float*)d_in[0];
    const void*  ei   = d_in[1];
    const float* Wl1  = (const float*)d_in[2];
    const float* Wr1  = (const float*)d_in[3];
    const float* att1 = (const float*)d_in[4];
    const float* b1   = (const float*)d_in[5];
    const float* Wl2  = (const float*)d_in[6];
    const float* Wr2  = (const float*)d_in[7];
    const float* att2 = (const float*)d_in[8];
    const float* b2   = (const float*)d_in[9];
    float* out = (float*)d_out;

    int N  = in_sizes[0] / F;
    int E  = in_sizes[1] / 2;
    int ET = E + N;

    float *xl, *xr, *hb;
    cudaGetSymbolAddress((void**)&xl, g_xl);
    cudaGetSymbolAddress((void**)&xr, g_xr);
    cudaGetSymbolAddress((void**)&hb, g_h);

    dim3 gg((N + 127) / 128, 2);
    int nbN  = (N + 255) / 256;
    int nbE  = (ET + 255) / 256;
    int nbW  = (N * 32 + 255) / 256;   // warp per dst node

    detect_mode<<<1, 1>>>(ei, in_sizes[1], N);

    // ---- CSR build (shared by both layers) ----
    zero_counts<<<nbN, 256>>>(N);
    count_deg<<<nbE, 256>>>(ei, E, N);
    scan_deg<<<1, 1024>>>(N);
    scatter_edges<<<nbE, 256>>>(ei, E, N);

    // ---- layer 1 (H=4, C=64) ----
    gemm256x2<<<gg, 256>>>(x, Wl1, xl, N);
    gemm256x2<<<gg, 256>>>(x, Wr1, xr, N);
    dst_logits<4><<<nbW, 256>>>(xl, xr, att1, N);
    dst_agg<4, 0><<<nbW, 256>>>(xl, b1, hb, N);

    // ---- layer 2 (H=1, C=256) ----
    gemm256x2<<<gg, 256>>>(hb, Wl2, xl, N);
    gemm256x2<<<gg, 256>>>(hb, Wr2, xr, N);
    dst_logits<1><<<nbW, 256>>>(xl, xr, att2, N);
    dst_agg<1, 1><<<nbW, 256>>>(xl, b2, out, N);
}

// round 4
// speedup vs baseline: 2.1539x; 1.0906x over previous
#include <cuda_runtime.h>
#include <cuda_bf16.h>
#include <cstdint>

// ---------------- problem constants ----------------
#define NMAX   50000
#define EMAX   800000
#define ETMAX  (EMAX + NMAX)
#define F      256            // feature width of every stage (H*C = 256)
#define NBLK   ((NMAX + 255) / 256)

// ---------------- scratch (static device arrays; no allocation) ----------------
__device__ float g_xl[(size_t)NMAX * F];
__device__ float g_xr[(size_t)NMAX * F];
__device__ float g_h [(size_t)NMAX * F];
__device__ int   g_deg[NMAX];
__device__ int   g_cur[NMAX];
__device__ int   g_row[NMAX + 1];
__device__ int   g_src[ETMAX];
__device__ int   g_bsum[NBLK + 1];
__device__ int   g_mode;   // 1 = edge_index is int64, 0 = int32

// ---------------- edge dtype detection (parallel) ----------------
__global__ void detect_mode(const void* ei, int n_elems, int N) {
    __shared__ int bad;
    if (threadIdx.x == 0) bad = 0;
    __syncthreads();
    const long long* p = (const long long*)ei;
    int lim = n_elems < 8192 ? n_elems : 8192;
    for (int i = threadIdx.x; i < lim; i += blockDim.x) {
        long long v = p[i];
        if (v < 0 || v >= (long long)N) bad = 1;
    }
    __syncthreads();
    if (threadIdx.x == 0) g_mode = bad ? 0 : 1;
}

__device__ __forceinline__ void load_edge(const void* ei, int mode, int E, int N,
                                          int w, int& s, int& d) {
    if (w >= E) { s = d = w - E; return; }   // self-loop
    if (mode) {
        const long long* p = (const long long*)ei;
        s = (int)p[w]; d = (int)p[E + w];
    } else {
        const int* p = (const int*)ei;
        s = p[w]; d = p[E + w];
    }
}

// ---------------- CSR build ----------------
__global__ void zero_counts(int N) {
    int i = blockIdx.x * blockDim.x + threadIdx.x;
    if (i < N) { g_deg[i] = 0; g_cur[i] = 0; }
}

__global__ void count_deg(const void* __restrict__ ei, int E, int N) {
    int e = blockIdx.x * blockDim.x + threadIdx.x;
    if (e >= E + N) return;
    int s, d; load_edge(ei, g_mode, E, N, e, s, d);
    atomicAdd(&g_deg[d], 1);
}

// per-block sums of degrees
__global__ void block_sums(int N) {
    __shared__ int sh[8];
    int i = blockIdx.x * 256 + threadIdx.x;
    int v = (i < N) ? g_deg[i] : 0;
#pragma unroll
    for (int o = 16; o; o >>= 1) v += __shfl_xor_sync(0xffffffffu, v, o);
    if ((threadIdx.x & 31) == 0) sh[threadIdx.x >> 5] = v;
    __syncthreads();
    if (threadIdx.x == 0) {
        int s = 0;
#pragma unroll
        for (int j = 0; j < 8; j++) s += sh[j];
        g_bsum[blockIdx.x] = s;
    }
}

// single-block exclusive scan of block sums
__global__ void scan_bsums(int nb, int N) {
    __shared__ int sh[NBLK + 1];
    int tid = threadIdx.x;
    for (int i = tid; i < nb; i += blockDim.x) sh[i] = g_bsum[i];
    __syncthreads();
    if (tid == 0) {
        int run = 0;
        for (int i = 0; i < nb; i++) { int v = sh[i]; sh[i] = run; run += v; }
        sh[nb] = run;
        g_row[N] = run;
    }
    __syncthreads();
    for (int i = tid; i <= nb; i += blockDim.x) g_bsum[i] = sh[i];
}

// per-block scan writes row offsets
__global__ void write_rows(int N) {
    __shared__ int warp_tot[8];
    int i = blockIdx.x * 256 + threadIdx.x;
    int lane = threadIdx.x & 31, wid = threadIdx.x >> 5;
    int v = (i < N) ? g_deg[i] : 0;
    int incl = v;
#pragma unroll
    for (int o = 1; o < 32; o <<= 1) {
        int t = __shfl_up_sync(0xffffffffu, incl, o);
        if (lane >= o) incl += t;
    }
    if (lane == 31) warp_tot[wid] = incl;
    __syncthreads();
    int wbase = 0;
#pragma unroll
    for (int j = 0; j < 8; j++) if (j < wid) wbase += warp_tot[j];
    if (i < N) g_row[i] = g_bsum[blockIdx.x] + wbase + incl - v;
}

__global__ void scatter_edges(const void* __restrict__ ei, int E, int N) {
    int e = blockIdx.x * blockDim.x + threadIdx.x;
    if (e >= E + N) return;
    int s, d; load_edge(ei, g_mode, E, N, e, s, d);
    int pos = g_row[d] + atomicAdd(&g_cur[d], 1);
    g_src[pos] = s;
}

// ---------------- GEMM: C[M,256] = A[M,256] * B[256,256] ----------------
#define FMA2(acc, a, b) \
    asm("fma.rn.f32x2 %0, %1, %2, %0;" : "+l"(acc) : "l"(a), "l"(b))

__device__ __forceinline__ float2 ull2f2(unsigned long long u) {
    float2 f;
    asm("mov.b64 {%0, %1}, %2;" : "=f"(f.x), "=f"(f.y) : "l"(u));
    return f;
}

__global__ void __launch_bounds__(256, 2) gemm256x2(
    const float* __restrict__ A, const float* __restrict__ B,
    float* __restrict__ C, int M)
{
    __shared__ float As2[16][256];   // [k][2m], each a duplicated
    __shared__ float BsA[16][64];
    __shared__ float BsB[16][64];

    const int tid = threadIdx.x;
    const int bm = blockIdx.x * 128;
    const int bn = blockIdx.y * 128;
    const int tx = tid & 15;
    const int ty = tid >> 4;

    const int arow = tid >> 1;
    const int aq0  = (tid & 1) * 2;
    const int brow = tid >> 4;
    const int bc8  = tid & 15;

    unsigned long long acc[8][4] = {};

    float4 a0, a1, b0, b1;
    {
        const float* ab = A + (size_t)(bm + arow) * F;
        if (bm + arow < M) {
            a0 = *(const float4*)(ab + aq0 * 4);
            a1 = *(const float4*)(ab + aq0 * 4 + 4);
        } else { a0 = a1 = make_float4(0.f,0.f,0.f,0.f); }
        const float* bb = B + (size_t)brow * F + bn + bc8 * 8;
        b0 = *(const float4*)bb;
        b1 = *(const float4*)(bb + 4);
    }

    for (int k0 = 0;;) {
        __syncthreads();
        {
            const float* av0 = &a0.x;
            const float* av1 = &a1.x;
#pragma unroll
            for (int t = 0; t < 4; t++) {
                int k  = aq0 * 4 + t;
                As2[k][2 * arow] = av0[t];  As2[k][2 * arow + 1] = av0[t];
                int k2 = aq0 * 4 + 4 + t;
                As2[k2][2 * arow] = av1[t]; As2[k2][2 * arow + 1] = av1[t];
            }
            *(float4*)&BsA[brow][bc8 * 4] = b0;
            *(float4*)&BsB[brow][bc8 * 4] = b1;
        }
        __syncthreads();

        k0 += 16;
        bool last = (k0 >= 256);
        if (!last) {
            const float* ab = A + (size_t)(bm + arow) * F + k0;
            if (bm + arow < M) {
                a0 = *(const float4*)(ab + aq0 * 4);
                a1 = *(const float4*)(ab + aq0 * 4 + 4);
            } else { a0 = a1 = make_float4(0.f,0.f,0.f,0.f); }
            const float* bb = B + (size_t)(k0 + brow) * F + bn + bc8 * 8;
            b0 = *(const float4*)bb;
            b1 = *(const float4*)(bb + 4);
        }

#pragma unroll
        for (int k = 0; k < 16; k++) {
            ulonglong2 adx = *(const ulonglong2*)&As2[k][ty * 16];
            ulonglong2 ady = *(const ulonglong2*)&As2[k][ty * 16 + 4];
            ulonglong2 adz = *(const ulonglong2*)&As2[k][ty * 16 + 8];
            ulonglong2 adw = *(const ulonglong2*)&As2[k][ty * 16 + 12];
            ulonglong2 bpA = *(const ulonglong2*)&BsA[k][tx * 4];
            ulonglong2 bpB = *(const ulonglong2*)&BsB[k][tx * 4];
            unsigned long long ad[8] = {adx.x, adx.y, ady.x, ady.y,
                                        adz.x, adz.y, adw.x, adw.y};
            unsigned long long bp[4] = {bpA.x, bpA.y, bpB.x, bpB.y};
#pragma unroll
            for (int i = 0; i < 8; i++)
#pragma unroll
                for (int jp = 0; jp < 4; jp++)
                    FMA2(acc[i][jp], ad[i], bp[jp]);
        }
        if (last) break;
    }

#pragma unroll
    for (int i = 0; i < 8; i++) {
        int r = bm + ty * 8 + i;
        if (r < M) {
            float2 c0 = ull2f2(acc[i][0]);
            float2 c1 = ull2f2(acc[i][1]);
            float2 c2 = ull2f2(acc[i][2]);
            float2 c3 = ull2f2(acc[i][3]);
            float* cp = C + (size_t)r * F + bn + tx * 8;
            *(float4*)cp       = make_float4(c0.x, c0.y, c1.x, c1.y);
            *(float4*)(cp + 4) = make_float4(c2.x, c2.y, c3.x, c3.y);
        }
    }
}

// ---------------- fused edge pass: online softmax + aggregation ----------------
// warp per destination node. Single pass over incident edges:
// running max m, denom d, accumulator acc rescaled online (flash-attention style).
// MODE 0: ELU epilogue (layer 1), MODE 1: bias only (layer 2).
template <int H, int MODE>
__global__ void __launch_bounds__(256) dst_fused(
    const float* __restrict__ xl, const float* __restrict__ xr,
    const float* __restrict__ att, const float* __restrict__ bias,
    float* __restrict__ out, int N)
{
    int w = (blockIdx.x * blockDim.x + threadIdx.x) >> 5;
    int lane = threadIdx.x & 31;
    if (w >= N) return;

    const float4* xr4 = (const float4*)(xr + (size_t)w * F);
    float4 r0 = xr4[lane], r1 = xr4[lane + 32];
    const float4* a4 = (const float4*)att;
    float4 a0 = a4[lane], a1 = a4[lane + 32];

    int row0 = g_row[w], row1 = g_row[w + 1];   // row1 > row0 (self-loop)

    const float NEG_INF = __int_as_float(0xFF800000);
    float m0 = NEG_INF, m1 = NEG_INF;
    float d0 = 0.f, d1 = 0.f;
    float4 acc0 = make_float4(0.f,0.f,0.f,0.f);
    float4 acc1 = make_float4(0.f,0.f,0.f,0.f);

    // prefetch first edge
    int s_cur = g_src[row0];
    const float4* xp = (const float4*)(xl + (size_t)s_cur * F);
    float4 l0 = xp[lane], l1 = xp[lane + 32];

    for (int i = row0; i < row1; i++) {
        float4 n0, n1;
        if (i + 1 < row1) {
            int s_nxt = g_src[i + 1];
            const float4* np = (const float4*)(xl + (size_t)s_nxt * F);
            n0 = np[lane]; n1 = np[lane + 32];
        }

        // logit for this edge
        float vx = l0.x + r0.x; vx = vx > 0.f ? vx : 0.2f * vx;
        float vy = l0.y + r0.y; vy = vy > 0.f ? vy : 0.2f * vy;
        float vz = l0.z + r0.z; vz = vz > 0.f ? vz : 0.2f * vz;
        float vw = l0.w + r0.w; vw = vw > 0.f ? vw : 0.2f * vw;
        float p0 = vx * a0.x + vy * a0.y + vz * a0.z + vw * a0.w;

        vx = l1.x + r1.x; vx = vx > 0.f ? vx : 0.2f * vx;
        vy = l1.y + r1.y; vy = vy > 0.f ? vy : 0.2f * vy;
        vz = l1.z + r1.z; vz = vz > 0.f ? vz : 0.2f * vz;
        vw = l1.w + r1.w; vw = vw > 0.f ? vw : 0.2f * vw;
        float p1 = vx * a1.x + vy * a1.y + vz * a1.z + vw * a1.w;

        if (H == 1) {
            float sum = p0 + p1;
#pragma unroll
            for (int o = 16; o; o >>= 1) sum += __shfl_xor_sync(0xffffffffu, sum, o);
            p0 = sum; p1 = sum;
        } else {   // H==4: butterfly within 16-lane group broadcasts head sums
#pragma unroll
            for (int o = 8; o; o >>= 1) {
                p0 += __shfl_xor_sync(0xffffffffu, p0, o);
                p1 += __shfl_xor_sync(0xffffffffu, p1, o);
            }
        }

        // online softmax update, pair 0
        {
            float nm = fmaxf(m0, p0);
            float sc = __expf(m0 - nm);     // 0 on first edge (m0 = -inf)
            float wt = __expf(p0 - nm);
            d0 = d0 * sc + wt;
            m0 = nm;
            acc0.x = acc0.x * sc + wt * l0.x;
            acc0.y = acc0.y * sc + wt * l0.y;
            acc0.z = acc0.z * sc + wt * l0.z;
            acc0.w = acc0.w * sc + wt * l0.w;
        }
        // pair 1
        {
            float nm = fmaxf(m1, p1);
            float sc = __expf(m1 - nm);
            float wt = __expf(p1 - nm);
            d1 = d1 * sc + wt;
            m1 = nm;
            acc1.x = acc1.x * sc + wt * l1.x;
            acc1.y = acc1.y * sc + wt * l1.y;
            acc1.z = acc1.z * sc + wt * l1.z;
            acc1.w = acc1.w * sc + wt * l1.w;
        }

        l0 = n0; l1 = n1;
    }

    float id0 = 1.f / d0, id1 = 1.f / d1;
    const float4* b4 = (const float4*)bias;
    float4 b0 = b4[lane], b1 = b4[lane + 32];
    acc0.x = acc0.x * id0 + b0.x; acc0.y = acc0.y * id0 + b0.y;
    acc0.z = acc0.z * id0 + b0.z; acc0.w = acc0.w * id0 + b0.w;
    acc1.x = acc1.x * id1 + b1.x; acc1.y = acc1.y * id1 + b1.y;
    acc1.z = acc1.z * id1 + b1.z; acc1.w = acc1.w * id1 + b1.w;

    if (MODE == 0) {   // ELU
        acc0.x = acc0.x > 0.f ? acc0.x : expm1f(acc0.x);
        acc0.y = acc0.y > 0.f ? acc0.y : expm1f(acc0.y);
        acc0.z = acc0.z > 0.f ? acc0.z : expm1f(acc0.z);
        acc0.w = acc0.w > 0.f ? acc0.w : expm1f(acc0.w);
        acc1.x = acc1.x > 0.f ? acc1.x : expm1f(acc1.x);
        acc1.y = acc1.y > 0.f ? acc1.y : expm1f(acc1.y);
        acc1.z = acc1.z > 0.f ? acc1.z : expm1f(acc1.z);
        acc1.w = acc1.w > 0.f ? acc1.w : expm1f(acc1.w);
    }

    float4* o4 = (float4*)(out + (size_t)w * F);
    o4[lane]      = acc0;
    o4[lane + 32] = acc1;
}

// ---------------- host ----------------
extern "C" void kernel_launch(void* const* d_in, const int* in_sizes, int n_in,
                              void* d_out, int out_size)
{
    const float* x    = (const float*)d_in[0];
    const void*  ei   = d_in[1];
    const float* Wl1  = (const float*)d_in[2];
    const float* Wr1  = (const float*)d_in[3];
    const float* att1 = (const float*)d_in[4];
    const float* b1   = (const float*)d_in[5];
    const float* Wl2  = (const float*)d_in[6];
    const float* Wr2  = (const float*)d_in[7];
    const float* att2 = (const float*)d_in[8];
    const float* b2   = (const float*)d_in[9];
    float* out = (float*)d_out;

    int N  = in_sizes[0] / F;
    int E  = in_sizes[1] / 2;
    int ET = E + N;

    float *xl, *xr, *hb;
    cudaGetSymbolAddress((void**)&xl, g_xl);
    cudaGetSymbolAddress((void**)&xr, g_xr);
    cudaGetSymbolAddress((void**)&hb, g_h);

    dim3 gg((N + 127) / 128, 2);
    int nbN  = (N + 255) / 256;
    int nbE  = (ET + 255) / 256;
    int nbW  = (N * 32 + 255) / 256;   // warp per dst node

    detect_mode<<<1, 256>>>(ei, in_sizes[1], N);

    // ---- CSR build (shared by both layers) ----
    zero_counts<<<nbN, 256>>>(N);
    count_deg<<<nbE, 256>>>(ei, E, N);
    block_sums<<<nbN, 256>>>(N);
    scan_bsums<<<1, 256>>>(nbN, N);
    write_rows<<<nbN, 256>>>(N);
    scatter_edges<<<nbE, 256>>>(ei, E, N);

    // ---- layer 1 (H=4, C=64) ----
    gemm256x2<<<gg, 256>>>(x, Wl1, xl, N);
    gemm256x2<<<gg, 256>>>(x, Wr1, xr, N);
    dst_fused<4, 0><<<nbW, 256>>>(xl, xr, att1, b1, hb, N);

    // ---- layer 2 (H=1, C=256) ----
    gemm256x2<<<gg, 256>>>(hb, Wl2, xl, N);
    gemm256x2<<<gg, 256>>>(hb, Wr2, xr, N);
    dst_fused<1, 1><<<nbW, 256>>>(xl, xr, att2, b2, out, N);
}

// round 6
// speedup vs baseline: 3.9647x; 1.8407x over previous
#include <cuda_runtime.h>
#include <cuda_bf16.h>
#include <cstdint>

// ---------------- problem constants ----------------
#define NMAX   50000
#define EMAX   800000
#define ETMAX  (EMAX + NMAX)
#define F      256
#define NBLK   ((NMAX + 255) / 256)
#define MTMAX  3136                       // padded m16-tile capacity

// ---------------- scratch ----------------
__device__ float g_xl[(size_t)NMAX * F];
__device__ float g_xr[(size_t)NMAX * F];
__device__ float g_h [(size_t)NMAX * F];
__device__ uint4 g_Ah[(size_t)MTMAX * 16 * 32];   // A fragments, bf16 hi
__device__ uint4 g_Al[(size_t)MTMAX * 16 * 32];   // A fragments, bf16 lo
__device__ uint4 g_Bph[4 * 16 * 16 * 32];         // W fragments, hi  [w][kt][nt2][lane]
__device__ uint4 g_Bpl[4 * 16 * 16 * 32];         // W fragments, lo
__device__ int   g_deg[NMAX];
__device__ int   g_cur[NMAX];
__device__ int   g_row[NMAX + 1];
__device__ int   g_src[ETMAX];
__device__ int   g_bsum[NBLK + 1];
__device__ int   g_mode;

// ---------------- helpers ----------------
__device__ __forceinline__ uint32_t bf2pack(float x, float y) {
    __nv_bfloat162 h = __floats2bfloat162_rn(x, y);
    return *(uint32_t*)&h;
}
__device__ __forceinline__ float bfhi(float x) {
    return __bfloat162float(__float2bfloat16_rn(x));
}

#define MMA16816(c, a, b0, b1)                                          \
    asm volatile(                                                        \
        "mma.sync.aligned.m16n8k16.row.col.f32.bf16.bf16.f32 "          \
        "{%0,%1,%2,%3}, {%4,%5,%6,%7}, {%8,%9}, {%0,%1,%2,%3};"         \
        : "+f"((c)[0]), "+f"((c)[1]), "+f"((c)[2]), "+f"((c)[3])        \
        : "r"((a).x), "r"((a).y), "r"((a).z), "r"((a).w),               \
          "r"(b0), "r"(b1))

// ---------------- edge dtype detection ----------------
__global__ void detect_mode(const void* ei, int n_elems, int N) {
    __shared__ int bad;
    if (threadIdx.x == 0) bad = 0;
    __syncthreads();
    const long long* p = (const long long*)ei;
    int lim = n_elems < 8192 ? n_elems : 8192;
    for (int i = threadIdx.x; i < lim; i += blockDim.x) {
        long long v = p[i];
        if (v < 0 || v >= (long long)N) bad = 1;
    }
    __syncthreads();
    if (threadIdx.x == 0) g_mode = bad ? 0 : 1;
}

__device__ __forceinline__ void load_edge(const void* ei, int mode, int E, int N,
                                          int w, int& s, int& d) {
    if (w >= E) { s = d = w - E; return; }
    if (mode) {
        const long long* p = (const long long*)ei;
        s = (int)p[w]; d = (int)p[E + w];
    } else {
        const int* p = (const int*)ei;
        s = p[w]; d = p[E + w];
    }
}

// ---------------- CSR build ----------------
__global__ void zero_counts(int N) {
    int i = blockIdx.x * blockDim.x + threadIdx.x;
    if (i < N) { g_deg[i] = 0; g_cur[i] = 0; }
}
__global__ void count_deg(const void* __restrict__ ei, int E, int N) {
    int e = blockIdx.x * blockDim.x + threadIdx.x;
    if (e >= E + N) return;
    int s, d; load_edge(ei, g_mode, E, N, e, s, d);
    atomicAdd(&g_deg[d], 1);
}
__global__ void block_sums(int N) {
    __shared__ int sh[8];
    int i = blockIdx.x * 256 + threadIdx.x;
    int v = (i < N) ? g_deg[i] : 0;
#pragma unroll
    for (int o = 16; o; o >>= 1) v += __shfl_xor_sync(0xffffffffu, v, o);
    if ((threadIdx.x & 31) == 0) sh[threadIdx.x >> 5] = v;
    __syncthreads();
    if (threadIdx.x == 0) {
        int s = 0;
#pragma unroll
        for (int j = 0; j < 8; j++) s += sh[j];
        g_bsum[blockIdx.x] = s;
    }
}
__global__ void scan_bsums(int nb, int N) {
    __shared__ int sh[NBLK + 1];
    int tid = threadIdx.x;
    for (int i = tid; i < nb; i += blockDim.x) sh[i] = g_bsum[i];
    __syncthreads();
    if (tid == 0) {
        int run = 0;
        for (int i = 0; i < nb; i++) { int v = sh[i]; sh[i] = run; run += v; }
        sh[nb] = run;
        g_row[N] = run;
    }
    __syncthreads();
    for (int i = tid; i <= nb; i += blockDim.x) g_bsum[i] = sh[i];
}
__global__ void write_rows(int N) {
    __shared__ int warp_tot[8];
    int i = blockIdx.x * 256 + threadIdx.x;
    int lane = threadIdx.x & 31, wid = threadIdx.x >> 5;
    int v = (i < N) ? g_deg[i] : 0;
    int incl = v;
#pragma unroll
    for (int o = 1; o < 32; o <<= 1) {
        int t = __shfl_up_sync(0xffffffffu, incl, o);
        if (lane >= o) incl += t;
    }
    if (lane == 31) warp_tot[wid] = incl;
    __syncthreads();
    int wbase = 0;
#pragma unroll
    for (int j = 0; j < 8; j++) if (j < wid) wbase += warp_tot[j];
    if (i < N) g_row[i] = g_bsum[blockIdx.x] + wbase + incl - v;
}
__global__ void scatter_edges(const void* __restrict__ ei, int E, int N) {
    int e = blockIdx.x * blockDim.x + threadIdx.x;
    if (e >= E + N) return;
    int s, d; load_edge(ei, g_mode, E, N, e, s, d);
    int pos = g_row[d] + atomicAdd(&g_cur[d], 1);
    g_src[pos] = s;
}

// ---------------- weight fragment pack (runs once) ----------------
// Bp[w][kt][nt2][lane] = uint4{ b0(n8=nt2*16), b1(n8), b0(n8+8), b1(n8+8) }
// b0 packs W[k][n],W[k+1][n] with k = kt*16 + 2*(lane&3); b1 same at k+8.
__global__ void prepack_B(const float* __restrict__ W0, const float* __restrict__ W1,
                          const float* __restrict__ W2, const float* __restrict__ W3)
{
    int idx = blockIdx.x * blockDim.x + threadIdx.x;   // 4*16*16*32 = 32768
    if (idx >= 4 * 16 * 16 * 32) return;
    int lane = idx & 31;
    int nt2  = (idx >> 5) & 15;
    int kt   = (idx >> 9) & 15;
    int w    = idx >> 13;
    const float* W = (w == 0) ? W0 : (w == 1) ? W1 : (w == 2) ? W2 : W3;

    int n = nt2 * 16 + (lane >> 2);
    int k = kt * 16 + ((lane & 3) << 1);

    float v[8];
    v[0] = W[(size_t)k * 256 + n];       v[1] = W[(size_t)(k+1) * 256 + n];
    v[2] = W[(size_t)(k+8) * 256 + n];   v[3] = W[(size_t)(k+9) * 256 + n];
    v[4] = W[(size_t)k * 256 + n+8];     v[5] = W[(size_t)(k+1) * 256 + n+8];
    v[6] = W[(size_t)(k+8) * 256 + n+8]; v[7] = W[(size_t)(k+9) * 256 + n+8];

    float h[8], l[8];
#pragma unroll
    for (int i = 0; i < 8; i++) { h[i] = bfhi(v[i]); l[i] = v[i] - h[i]; }

    int off = w * 8192 + ((kt << 4) | nt2) * 32 + lane;
    g_Bph[off] = make_uint4(bf2pack(h[0],h[1]), bf2pack(h[2],h[3]),
                            bf2pack(h[4],h[5]), bf2pack(h[6],h[7]));
    g_Bpl[off] = make_uint4(bf2pack(l[0],l[1]), bf2pack(l[2],l[3]),
                            bf2pack(l[4],l[5]), bf2pack(l[6],l[7]));
}

// ---------------- A fragment pack (runs per layer) ----------------
// Ap[mt][kt][lane] = uint4{a0,a1,a2,a3}; a0 = A[r][c,c+1], a1 = A[r+8][c..],
// a2 = A[r][c+8..], a3 = A[r+8][c+8..], r = mt*16+(lane>>2), c = kt*16+2*(lane&3).
__global__ void prepack_A(const float* __restrict__ A, int M, int total) {
    int idx = blockIdx.x * blockDim.x + threadIdx.x;
    if (idx >= total) return;
    int lane = idx & 31;
    int kt   = (idx >> 5) & 15;
    int mt   = idx >> 9;
    int r = mt * 16 + (lane >> 2);
    int c = kt * 16 + ((lane & 3) << 1);

    float2 z = make_float2(0.f, 0.f);
    float2 v0 = (r     < M) ? *(const float2*)(A + (size_t)r * 256 + c)       : z;
    float2 v1 = (r + 8 < M) ? *(const float2*)(A + (size_t)(r+8) * 256 + c)   : z;
    float2 v2 = (r     < M) ? *(const float2*)(A + (size_t)r * 256 + c + 8)   : z;
    float2 v3 = (r + 8 < M) ? *(const float2*)(A + (size_t)(r+8) * 256 + c+8) : z;

    float h0x = bfhi(v0.x), h0y = bfhi(v0.y);
    float h1x = bfhi(v1.x), h1y = bfhi(v1.y);
    float h2x = bfhi(v2.x), h2y = bfhi(v2.y);
    float h3x = bfhi(v3.x), h3y = bfhi(v3.y);

    g_Ah[idx] = make_uint4(bf2pack(h0x, h0y), bf2pack(h1x, h1y),
                           bf2pack(h2x, h2y), bf2pack(h3x, h3y));
    g_Al[idx] = make_uint4(bf2pack(v0.x-h0x, v0.y-h0y), bf2pack(v1.x-h1x, v1.y-h1y),
                           bf2pack(v2.x-h2x, v2.y-h2y), bf2pack(v3.x-h3x, v3.y-h3y));
}

// ---------------- GEMM via mma.sync bf16 split-3 ----------------
// Block = 8 warps: warp grid 2(m) x 4(n). Warp tile 64(m) x 32(n).
// C[M,256] = A[M,256] @ W[256,256];  D = Ah Bh + Al Bh + Ah Bl.
__global__ void __launch_bounds__(256) gemm_mma(
    const uint4* __restrict__ Bh, const uint4* __restrict__ Bl,
    float* __restrict__ C, int M)
{
    const int lane = threadIdx.x & 31;
    const int wid  = threadIdx.x >> 5;
    const int wm   = wid >> 2;
    const int wn   = wid & 3;
    const int mt0   = blockIdx.x * 8 + wm * 4;
    const int nt2_0 = blockIdx.y * 8 + wn * 2;

    float c[4][4][4];
#pragma unroll
    for (int i = 0; i < 4; i++)
#pragma unroll
        for (int j = 0; j < 4; j++)
#pragma unroll
            for (int q = 0; q < 4; q++) c[i][j][q] = 0.f;

#pragma unroll 1
    for (int ph = 0; ph < 3; ph++) {
        const uint4* Ap = (ph == 1) ? g_Al : g_Ah;
        const uint4* Bp = (ph == 2) ? Bl : Bh;
#pragma unroll 4
        for (int kt = 0; kt < 16; kt++) {
            uint4 B0 = Bp[(((kt << 4) |  nt2_0     ) << 5) | lane];
            uint4 B1 = Bp[(((kt << 4) | (nt2_0 + 1)) << 5) | lane];
            uint4 Af[4];
#pragma unroll
            for (int mf = 0; mf < 4; mf++)
                Af[mf] = Ap[((((mt0 + mf) << 4) | kt) << 5) | lane];
#pragma unroll
            for (int mf = 0; mf < 4; mf++) {
                MMA16816(c[mf][0], Af[mf], B0.x, B0.y);
                MMA16816(c[mf][1], Af[mf], B0.z, B0.w);
                MMA16816(c[mf][2], Af[mf], B1.x, B1.y);
                MMA16816(c[mf][3], Af[mf], B1.z, B1.w);
            }
        }
    }

    // epilogue
#pragma unroll
    for (int mf = 0; mf < 4; mf++) {
        int m = (mt0 + mf) * 16 + (lane >> 2);
#pragma unroll
        for (int j = 0; j < 4; j++) {
            int nb = (nt2_0 + (j >> 1)) * 16 + (j & 1) * 8 + ((lane & 3) << 1);
            if (m < M)
                *(float2*)(C + (size_t)m * 256 + nb) = make_float2(c[mf][j][0], c[mf][j][1]);
            if (m + 8 < M)
                *(float2*)(C + (size_t)(m + 8) * 256 + nb) = make_float2(c[mf][j][2], c[mf][j][3]);
        }
    }
}

// ---------------- fused edge pass (unchanged) ----------------
template <int H, int MODE>
__global__ void __launch_bounds__(256) dst_fused(
    const float* __restrict__ xl, const float* __restrict__ xr,
    const float* __restrict__ att, const float* __restrict__ bias,
    float* __restrict__ out, int N)
{
    int w = (blockIdx.x * blockDim.x + threadIdx.x) >> 5;
    int lane = threadIdx.x & 31;
    if (w >= N) return;

    const float4* xr4 = (const float4*)(xr + (size_t)w * F);
    float4 r0 = xr4[lane], r1 = xr4[lane + 32];
    const float4* a4 = (const float4*)att;
    float4 a0 = a4[lane], a1 = a4[lane + 32];

    int row0 = g_row[w], row1 = g_row[w + 1];

    const float NEG_INF = __int_as_float(0xFF800000);
    float m0 = NEG_INF, m1 = NEG_INF;
    float d0 = 0.f, d1 = 0.f;
    float4 acc0 = make_float4(0.f,0.f,0.f,0.f);
    float4 acc1 = make_float4(0.f,0.f,0.f,0.f);

    int s_cur = g_src[row0];
    const float4* xp = (const float4*)(xl + (size_t)s_cur * F);
    float4 l0 = xp[lane], l1 = xp[lane + 32];

    for (int i = row0; i < row1; i++) {
        float4 n0, n1;
        if (i + 1 < row1) {
            int s_nxt = g_src[i + 1];
            const float4* np = (const float4*)(xl + (size_t)s_nxt * F);
            n0 = np[lane]; n1 = np[lane + 32];
        }

        float vx = l0.x + r0.x; vx = vx > 0.f ? vx : 0.2f * vx;
        float vy = l0.y + r0.y; vy = vy > 0.f ? vy : 0.2f * vy;
        float vz = l0.z + r0.z; vz = vz > 0.f ? vz : 0.2f * vz;
        float vw = l0.w + r0.w; vw = vw > 0.f ? vw : 0.2f * vw;
        float p0 = vx * a0.x + vy * a0.y + vz * a0.z + vw * a0.w;

        vx = l1.x + r1.x; vx = vx > 0.f ? vx : 0.2f * vx;
        vy = l1.y + r1.y; vy = vy > 0.f ? vy : 0.2f * vy;
        vz = l1.z + r1.z; vz = vz > 0.f ? vz : 0.2f * vz;
        vw = l1.w + r1.w; vw = vw > 0.f ? vw : 0.2f * vw;
        float p1 = vx * a1.x + vy * a1.y + vz * a1.z + vw * a1.w;

        if (H == 1) {
            float sum = p0 + p1;
#pragma unroll
            for (int o = 16; o; o >>= 1) sum += __shfl_xor_sync(0xffffffffu, sum, o);
            p0 = sum; p1 = sum;
        } else {
#pragma unroll
            for (int o = 8; o; o >>= 1) {
                p0 += __shfl_xor_sync(0xffffffffu, p0, o);
                p1 += __shfl_xor_sync(0xffffffffu, p1, o);
            }
        }

        {
            float nm = fmaxf(m0, p0);
            float sc = __expf(m0 - nm);
            float wt = __expf(p0 - nm);
            d0 = d0 * sc + wt; m0 = nm;
            acc0.x = acc0.x * sc + wt * l0.x;
            acc0.y = acc0.y * sc + wt * l0.y;
            acc0.z = acc0.z * sc + wt * l0.z;
            acc0.w = acc0.w * sc + wt * l0.w;
        }
        {
            float nm = fmaxf(m1, p1);
            float sc = __expf(m1 - nm);
            float wt = __expf(p1 - nm);
            d1 = d1 * sc + wt; m1 = nm;
            acc1.x = acc1.x * sc + wt * l1.x;
            acc1.y = acc1.y * sc + wt * l1.y;
            acc1.z = acc1.z * sc + wt * l1.z;
            acc1.w = acc1.w * sc + wt * l1.w;
        }

        l0 = n0; l1 = n1;
    }

    float id0 = 1.f / d0, id1 = 1.f / d1;
    const float4* b4 = (const float4*)bias;
    float4 b0 = b4[lane], b1 = b4[lane + 32];
    acc0.x = acc0.x * id0 + b0.x; acc0.y = acc0.y * id0 + b0.y;
    acc0.z = acc0.z * id0 + b0.z; acc0.w = acc0.w * id0 + b0.w;
    acc1.x = acc1.x * id1 + b1.x; acc1.y = acc1.y * id1 + b1.y;
    acc1.z = acc1.z * id1 + b1.z; acc1.w = acc1.w * id1 + b1.w;

    if (MODE == 0) {
        acc0.x = acc0.x > 0.f ? acc0.x : expm1f(acc0.x);
        acc0.y = acc0.y > 0.f ? acc0.y : expm1f(acc0.y);
        acc0.z = acc0.z > 0.f ? acc0.z : expm1f(acc0.z);
        acc0.w = acc0.w > 0.f ? acc0.w : expm1f(acc0.w);
        acc1.x = acc1.x > 0.f ? acc1.x : expm1f(acc1.x);
        acc1.y = acc1.y > 0.f ? acc1.y : expm1f(acc1.y);
        acc1.z = acc1.z > 0.f ? acc1.z : expm1f(acc1.z);
        acc1.w = acc1.w > 0.f ? acc1.w : expm1f(acc1.w);
    }

    float4* o4 = (float4*)(out + (size_t)w * F);
    o4[lane]      = acc0;
    o4[lane + 32] = acc1;
}

// ---------------- host ----------------
extern "C" void kernel_launch(void* const* d_in, const int* in_sizes, int n_in,
                              void* d_out, int out_size)
{
    const float* x    = (const float*)d_in[0];
    const void*  ei   = d_in[1];
    const float* Wl1  = (const float*)d_in[2];
    const float* Wr1  = (const float*)d_in[3];
    const float* att1 = (const float*)d_in[4];
    const float* b1   = (const float*)d_in[5];
    const float* Wl2  = (const float*)d_in[6];
    const float* Wr2  = (const float*)d_in[7];
    const float* att2 = (const float*)d_in[8];
    const float* b2   = (const float*)d_in[9];
    float* out = (float*)d_out;

    int N  = in_sizes[0] / F;
    int E  = in_sizes[1] / 2;
    int ET = E + N;

    float *xl, *xr, *hb;
    uint4 *bph, *bpl;
    cudaGetSymbolAddress((void**)&xl,  g_xl);
    cudaGetSymbolAddress((void**)&xr,  g_xr);
    cudaGetSymbolAddress((void**)&hb,  g_h);
    cudaGetSymbolAddress((void**)&bph, g_Bph);
    cudaGetSymbolAddress((void**)&bpl, g_Bpl);

    int nbN = (N + 255) / 256;
    int nbE = (ET + 255) / 256;
    int nbW = (N * 32 + 255) / 256;

    int mtiles = (N + 15) / 16;
    int gx = (mtiles + 7) / 8;           // GEMM grid x
    dim3 gemm_grid(gx, 2);
    int atotal = gx * 8 * 16 * 32;       // A-pack threads
    int apb = (atotal + 255) / 256;

    detect_mode<<<1, 256>>>(ei, in_sizes[1], N);

    // CSR build
    zero_counts<<<nbN, 256>>>(N);
    count_deg<<<nbE, 256>>>(ei, E, N);
    block_sums<<<nbN, 256>>>(N);
    scan_bsums<<<1, 256>>>(nbN, N);
    write_rows<<<nbN, 256>>>(N);
    scatter_edges<<<nbE, 256>>>(ei, E, N);

    // weight fragments (once)
    prepack_B<<<128, 256>>>(Wl1, Wr1, Wl2, Wr2);

    // ---- layer 1 (H=4) ----
    prepack_A<<<apb, 256>>>(x, N, atotal);
    gemm_mma<<<gemm_grid, 256>>>(bph + 0 * 8192, bpl + 0 * 8192, xl, N);
    gemm_mma<<<gemm_grid, 256>>>(bph + 1 * 8192, bpl + 1 * 8192, xr, N);
    dst_fused<4, 0><<<nbW, 256>>>(xl, xr, att1, b1, hb, N);

    // ---- layer 2 (H=1) ----
    prepack_A<<<apb, 256>>>(hb, N, atotal);
    gemm_mma<<<gemm_grid, 256>>>(bph + 2 * 8192, bpl + 2 * 8192, xl, N);
    gemm_mma<<<gemm_grid, 256>>>(bph + 3 * 8192, bpl + 3 * 8192, xr, N);
    dst_fused<1, 1><<<nbW, 256>>>(xl, xr, att2, b2, out, N);
}

// round 7
// speedup vs baseline: 4.1044x; 1.0352x over previous
#include <cuda_runtime.h>
#include <cuda_bf16.h>
#include <cstdint>

// ---------------- problem constants ----------------
#define NMAX   50000
#define EMAX   800000
#define ETMAX  (EMAX + NMAX)
#define F      256
#define NBLK   ((NMAX + 255) / 256)
#define MTMAX  3136                       // padded m16-tile capacity

// ---------------- scratch ----------------
__device__ float g_xl[(size_t)NMAX * F];
__device__ float g_xr[(size_t)NMAX * F];
__device__ float g_h [(size_t)NMAX * F];
__device__ uint4 g_Ah[(size_t)MTMAX * 16 * 32];   // A fragments, bf16 hi
__device__ uint4 g_Al[(size_t)MTMAX * 16 * 32];   // A fragments, bf16 lo
__device__ uint4 g_Bph[4 * 16 * 16 * 32];         // W fragments, hi
__device__ uint4 g_Bpl[4 * 16 * 16 * 32];         // W fragments, lo
__device__ int   g_deg[NMAX];
__device__ int   g_cur[NMAX];
__device__ int   g_row[NMAX + 1];
__device__ int   g_src[ETMAX];
__device__ int   g_bsum[NBLK + 1];
__device__ int   g_mode;

// ---------------- helpers ----------------
__device__ __forceinline__ uint32_t bf2pack(float x, float y) {
    __nv_bfloat162 h = __floats2bfloat162_rn(x, y);
    return *(uint32_t*)&h;
}
__device__ __forceinline__ float bfhi(float x) {
    return __bfloat162float(__float2bfloat16_rn(x));
}

#define MMA16816(c, a, b0, b1)                                          \
    asm volatile(                                                        \
        "mma.sync.aligned.m16n8k16.row.col.f32.bf16.bf16.f32 "          \
        "{%0,%1,%2,%3}, {%4,%5,%6,%7}, {%8,%9}, {%0,%1,%2,%3};"         \
        : "+f"((c)[0]), "+f"((c)[1]), "+f"((c)[2]), "+f"((c)[3])        \
        : "r"((a).x), "r"((a).y), "r"((a).z), "r"((a).w),               \
          "r"(b0), "r"(b1))

// ---------------- edge dtype detection ----------------
__global__ void detect_mode(const void* ei, int n_elems, int N) {
    __shared__ int bad;
    if (threadIdx.x == 0) bad = 0;
    __syncthreads();
    const long long* p = (const long long*)ei;
    int lim = n_elems < 8192 ? n_elems : 8192;
    for (int i = threadIdx.x; i < lim; i += blockDim.x) {
        long long v = p[i];
        if (v < 0 || v >= (long long)N) bad = 1;
    }
    __syncthreads();
    if (threadIdx.x == 0) g_mode = bad ? 0 : 1;
}

__device__ __forceinline__ void load_edge(const void* ei, int mode, int E, int N,
                                          int w, int& s, int& d) {
    if (w >= E) { s = d = w - E; return; }
    if (mode) {
        const long long* p = (const long long*)ei;
        s = (int)p[w]; d = (int)p[E + w];
    } else {
        const int* p = (const int*)ei;
        s = p[w]; d = p[E + w];
    }
}

// ---------------- CSR build ----------------
__global__ void zero_counts(int N) {
    int i = blockIdx.x * blockDim.x + threadIdx.x;
    if (i < N) { g_deg[i] = 0; g_cur[i] = 0; }
}
__global__ void count_deg(const void* __restrict__ ei, int E, int N) {
    int e = blockIdx.x * blockDim.x + threadIdx.x;
    if (e >= E + N) return;
    int s, d; load_edge(ei, g_mode, E, N, e, s, d);
    atomicAdd(&g_deg[d], 1);
}
__global__ void block_sums(int N) {
    __shared__ int sh[8];
    int i = blockIdx.x * 256 + threadIdx.x;
    int v = (i < N) ? g_deg[i] : 0;
#pragma unroll
    for (int o = 16; o; o >>= 1) v += __shfl_xor_sync(0xffffffffu, v, o);
    if ((threadIdx.x & 31) == 0) sh[threadIdx.x >> 5] = v;
    __syncthreads();
    if (threadIdx.x == 0) {
        int s = 0;
#pragma unroll
        for (int j = 0; j < 8; j++) s += sh[j];
        g_bsum[blockIdx.x] = s;
    }
}
__global__ void scan_bsums(int nb, int N) {
    __shared__ int sh[NBLK + 1];
    int tid = threadIdx.x;
    for (int i = tid; i < nb; i += blockDim.x) sh[i] = g_bsum[i];
    __syncthreads();
    if (tid == 0) {
        int run = 0;
        for (int i = 0; i < nb; i++) { int v = sh[i]; sh[i] = run; run += v; }
        sh[nb] = run;
        g_row[N] = run;
    }
    __syncthreads();
    for (int i = tid; i <= nb; i += blockDim.x) g_bsum[i] = sh[i];
}
__global__ void write_rows(int N) {
    __shared__ int warp_tot[8];
    int i = blockIdx.x * 256 + threadIdx.x;
    int lane = threadIdx.x & 31, wid = threadIdx.x >> 5;
    int v = (i < N) ? g_deg[i] : 0;
    int incl = v;
#pragma unroll
    for (int o = 1; o < 32; o <<= 1) {
        int t = __shfl_up_sync(0xffffffffu, incl, o);
        if (lane >= o) incl += t;
    }
    if (lane == 31) warp_tot[wid] = incl;
    __syncthreads();
    int wbase = 0;
#pragma unroll
    for (int j = 0; j < 8; j++) if (j < wid) wbase += warp_tot[j];
    if (i < N) g_row[i] = g_bsum[blockIdx.x] + wbase + incl - v;
}
__global__ void scatter_edges(const void* __restrict__ ei, int E, int N) {
    int e = blockIdx.x * blockDim.x + threadIdx.x;
    if (e >= E + N) return;
    int s, d; load_edge(ei, g_mode, E, N, e, s, d);
    int pos = g_row[d] + atomicAdd(&g_cur[d], 1);
    g_src[pos] = s;
}

// ---------------- weight fragment pack (runs once) ----------------
__global__ void prepack_B(const float* __restrict__ W0, const float* __restrict__ W1,
                          const float* __restrict__ W2, const float* __restrict__ W3)
{
    int idx = blockIdx.x * blockDim.x + threadIdx.x;   // 4*16*16*32 = 32768
    if (idx >= 4 * 16 * 16 * 32) return;
    int lane = idx & 31;
    int nt2  = (idx >> 5) & 15;
    int kt   = (idx >> 9) & 15;
    int w    = idx >> 13;
    const float* W = (w == 0) ? W0 : (w == 1) ? W1 : (w == 2) ? W2 : W3;

    int n = nt2 * 16 + (lane >> 2);
    int k = kt * 16 + ((lane & 3) << 1);

    float v[8];
    v[0] = W[(size_t)k * 256 + n];       v[1] = W[(size_t)(k+1) * 256 + n];
    v[2] = W[(size_t)(k+8) * 256 + n];   v[3] = W[(size_t)(k+9) * 256 + n];
    v[4] = W[(size_t)k * 256 + n+8];     v[5] = W[(size_t)(k+1) * 256 + n+8];
    v[6] = W[(size_t)(k+8) * 256 + n+8]; v[7] = W[(size_t)(k+9) * 256 + n+8];

    float h[8], l[8];
#pragma unroll
    for (int i = 0; i < 8; i++) { h[i] = bfhi(v[i]); l[i] = v[i] - h[i]; }

    int off = w * 8192 + ((kt << 4) | nt2) * 32 + lane;
    g_Bph[off] = make_uint4(bf2pack(h[0],h[1]), bf2pack(h[2],h[3]),
                            bf2pack(h[4],h[5]), bf2pack(h[6],h[7]));
    g_Bpl[off] = make_uint4(bf2pack(l[0],l[1]), bf2pack(l[2],l[3]),
                            bf2pack(l[4],l[5]), bf2pack(l[6],l[7]));
}

// ---------------- A fragment pack (runs per layer) ----------------
__global__ void prepack_A(const float* __restrict__ A, int M, int total) {
    int idx = blockIdx.x * blockDim.x + threadIdx.x;
    if (idx >= total) return;
    int lane = idx & 31;
    int kt   = (idx >> 5) & 15;
    int mt   = idx >> 9;
    int r = mt * 16 + (lane >> 2);
    int c = kt * 16 + ((lane & 3) << 1);

    float2 z = make_float2(0.f, 0.f);
    float2 v0 = (r     < M) ? *(const float2*)(A + (size_t)r * 256 + c)       : z;
    float2 v1 = (r + 8 < M) ? *(const float2*)(A + (size_t)(r+8) * 256 + c)   : z;
    float2 v2 = (r     < M) ? *(const float2*)(A + (size_t)r * 256 + c + 8)   : z;
    float2 v3 = (r + 8 < M) ? *(const float2*)(A + (size_t)(r+8) * 256 + c+8) : z;

    float h0x = bfhi(v0.x), h0y = bfhi(v0.y);
    float h1x = bfhi(v1.x), h1y = bfhi(v1.y);
    float h2x = bfhi(v2.x), h2y = bfhi(v2.y);
    float h3x = bfhi(v3.x), h3y = bfhi(v3.y);

    g_Ah[idx] = make_uint4(bf2pack(h0x, h0y), bf2pack(h1x, h1y),
                           bf2pack(h2x, h2y), bf2pack(h3x, h3y));
    g_Al[idx] = make_uint4(bf2pack(v0.x-h0x, v0.y-h0y), bf2pack(v1.x-h1x, v1.y-h1y),
                           bf2pack(v2.x-h2x, v2.y-h2y), bf2pack(v3.x-h3x, v3.y-h3y));
}

// ---------------- GEMM via mma.sync bf16 split-3 ----------------
// Block = 8 warps spanning all 256 N-cols (32 each); CTA covers 64 rows.
// A fragments read once per GEMM (8-warp L1 broadcast reuse).
__global__ void __launch_bounds__(256) gemm_mma(
    const uint4* __restrict__ Bh, const uint4* __restrict__ Bl,
    float* __restrict__ C, int M)
{
    const int lane = threadIdx.x & 31;
    const int wid  = threadIdx.x >> 5;
    const int mt0   = blockIdx.x * 4;
    const int nt2_0 = wid * 2;

    float c[4][4][4];
#pragma unroll
    for (int i = 0; i < 4; i++)
#pragma unroll
        for (int j = 0; j < 4; j++)
#pragma unroll
            for (int q = 0; q < 4; q++) c[i][j][q] = 0.f;

#pragma unroll 1
    for (int ph = 0; ph < 3; ph++) {
        const uint4* Ap = (ph == 1) ? g_Al : g_Ah;
        const uint4* Bp = (ph == 2) ? Bl : Bh;
#pragma unroll 4
        for (int kt = 0; kt < 16; kt++) {
            uint4 B0 = Bp[(((kt << 4) |  nt2_0     ) << 5) | lane];
            uint4 B1 = Bp[(((kt << 4) | (nt2_0 + 1)) << 5) | lane];
            uint4 Af[4];
#pragma unroll
            for (int mf = 0; mf < 4; mf++)
                Af[mf] = Ap[((((mt0 + mf) << 4) | kt) << 5) | lane];
#pragma unroll
            for (int mf = 0; mf < 4; mf++) {
                MMA16816(c[mf][0], Af[mf], B0.x, B0.y);
                MMA16816(c[mf][1], Af[mf], B0.z, B0.w);
                MMA16816(c[mf][2], Af[mf], B1.x, B1.y);
                MMA16816(c[mf][3], Af[mf], B1.z, B1.w);
            }
        }
    }

#pragma unroll
    for (int mf = 0; mf < 4; mf++) {
        int m = (mt0 + mf) * 16 + (lane >> 2);
#pragma unroll
        for (int j = 0; j < 4; j++) {
            int nb = (nt2_0 + (j >> 1)) * 16 + (j & 1) * 8 + ((lane & 3) << 1);
            if (m < M)
                *(float2*)(C + (size_t)m * 256 + nb) = make_float2(c[mf][j][0], c[mf][j][1]);
            if (m + 8 < M)
                *(float2*)(C + (size_t)(m + 8) * 256 + nb) = make_float2(c[mf][j][2], c[mf][j][3]);
        }
    }
}

// ---------------- fused edge pass ----------------
template <int H, int MODE>
__global__ void __launch_bounds__(256) dst_fused(
    const float* __restrict__ xl, const float* __restrict__ xr,
    const float* __restrict__ att, const float* __restrict__ bias,
    float* __restrict__ out, int N)
{
    int w = (blockIdx.x * blockDim.x + threadIdx.x) >> 5;
    int lane = threadIdx.x & 31;
    if (w >= N) return;

    const float4* xr4 = (const float4*)(xr + (size_t)w * F);
    float4 r0 = xr4[lane], r1 = xr4[lane + 32];
    const float4* a4 = (const float4*)att;
    float4 a0 = a4[lane], a1 = a4[lane + 32];

    int row0 = g_row[w], row1 = g_row[w + 1];

    const float NEG_INF = __int_as_float(0xFF800000);
    float m0 = NEG_INF, m1 = NEG_INF;
    float d0 = 0.f, d1 = 0.f;
    float4 acc0 = make_float4(0.f,0.f,0.f,0.f);
    float4 acc1 = make_float4(0.f,0.f,0.f,0.f);

    int s_cur = g_src[row0];
    const float4* xp = (const float4*)(xl + (size_t)s_cur * F);
    float4 l0 = xp[lane], l1 = xp[lane + 32];

    for (int i = row0; i < row1; i++) {
        float4 n0, n1;
        if (i + 1 < row1) {
            int s_nxt = g_src[i + 1];
            const float4* np = (const float4*)(xl + (size_t)s_nxt * F);
            n0 = np[lane]; n1 = np[lane + 32];
        }

        float vx = l0.x + r0.x; vx = vx > 0.f ? vx : 0.2f * vx;
        float vy = l0.y + r0.y; vy = vy > 0.f ? vy : 0.2f * vy;
        float vz = l0.z + r0.z; vz = vz > 0.f ? vz : 0.2f * vz;
        float vw = l0.w + r0.w; vw = vw > 0.f ? vw : 0.2f * vw;
        float p0 = vx * a0.x + vy * a0.y + vz * a0.z + vw * a0.w;

        vx = l1.x + r1.x; vx = vx > 0.f ? vx : 0.2f * vx;
        vy = l1.y + r1.y; vy = vy > 0.f ? vy : 0.2f * vy;
        vz = l1.z + r1.z; vz = vz > 0.f ? vz : 0.2f * vz;
        vw = l1.w + r1.w; vw = vw > 0.f ? vw : 0.2f * vw;
        float p1 = vx * a1.x + vy * a1.y + vz * a1.z + vw * a1.w;

        if (H == 1) {
            float sum = p0 + p1;
#pragma unroll
            for (int o = 16; o; o >>= 1) sum += __shfl_xor_sync(0xffffffffu, sum, o);
            p0 = sum; p1 = sum;
        } else {
#pragma unroll
            for (int o = 8; o; o >>= 1) {
                p0 += __shfl_xor_sync(0xffffffffu, p0, o);
                p1 += __shfl_xor_sync(0xffffffffu, p1, o);
            }
        }

        {
            float nm = fmaxf(m0, p0);
            float sc = __expf(m0 - nm);
            float wt = __expf(p0 - nm);
            d0 = d0 * sc + wt; m0 = nm;
            acc0.x = acc0.x * sc + wt * l0.x;
            acc0.y = acc0.y * sc + wt * l0.y;
            acc0.z = acc0.z * sc + wt * l0.z;
            acc0.w = acc0.w * sc + wt * l0.w;
        }
        {
            float nm = fmaxf(m1, p1);
            float sc = __expf(m1 - nm);
            float wt = __expf(p1 - nm);
            d1 = d1 * sc + wt; m1 = nm;
            acc1.x = acc1.x * sc + wt * l1.x;
            acc1.y = acc1.y * sc + wt * l1.y;
            acc1.z = acc1.z * sc + wt * l1.z;
            acc1.w = acc1.w * sc + wt * l1.w;
        }

        l0 = n0; l1 = n1;
    }

    float id0 = 1.f / d0, id1 = 1.f / d1;
    const float4* b4 = (const float4*)bias;
    float4 b0 = b4[lane], b1 = b4[lane + 32];
    acc0.x = acc0.x * id0 + b0.x; acc0.y = acc0.y * id0 + b0.y;
    acc0.z = acc0.z * id0 + b0.z; acc0.w = acc0.w * id0 + b0.w;
    acc1.x = acc1.x * id1 + b1.x; acc1.y = acc1.y * id1 + b1.y;
    acc1.z = acc1.z * id1 + b1.z; acc1.w = acc1.w * id1 + b1.w;

    if (MODE == 0) {
        acc0.x = acc0.x > 0.f ? acc0.x : expm1f(acc0.x);
        acc0.y = acc0.y > 0.f ? acc0.y : expm1f(acc0.y);
        acc0.z = acc0.z > 0.f ? acc0.z : expm1f(acc0.z);
        acc0.w = acc0.w > 0.f ? acc0.w : expm1f(acc0.w);
        acc1.x = acc1.x > 0.f ? acc1.x : expm1f(acc1.x);
        acc1.y = acc1.y > 0.f ? acc1.y : expm1f(acc1.y);
        acc1.z = acc1.z > 0.f ? acc1.z : expm1f(acc1.z);
        acc1.w = acc1.w > 0.f ? acc1.w : expm1f(acc1.w);
    }

    float4* o4 = (float4*)(out + (size_t)w * F);
    o4[lane]      = acc0;
    o4[lane + 32] = acc1;
}

// ---------------- host ----------------
extern "C" void kernel_launch(void* const* d_in, const int* in_sizes, int n_in,
                              void* d_out, int out_size)
{
    const float* x    = (const float*)d_in[0];
    const void*  ei   = d_in[1];
    const float* Wl1  = (const float*)d_in[2];
    const float* Wr1  = (const float*)d_in[3];
    const float* att1 = (const float*)d_in[4];
    const float* b1   = (const float*)d_in[5];
    const float* Wl2  = (const float*)d_in[6];
    const float* Wr2  = (const float*)d_in[7];
    const float* att2 = (const float*)d_in[8];
    const float* b2   = (const float*)d_in[9];
    float* out = (float*)d_out;

    int N  = in_sizes[0] / F;
    int E  = in_sizes[1] / 2;
    int ET = E + N;

    float *xl, *xr, *hb;
    uint4 *bph, *bpl;
    cudaGetSymbolAddress((void**)&xl,  g_xl);
    cudaGetSymbolAddress((void**)&xr,  g_xr);
    cudaGetSymbolAddress((void**)&hb,  g_h);
    cudaGetSymbolAddress((void**)&bph, g_Bph);
    cudaGetSymbolAddress((void**)&bpl, g_Bpl);

    // lazy-created side streams/events (created on first = correctness call,
    // reused during capture; resource caching only, same GPU work every call)
    static cudaStream_t sA = nullptr, sB = nullptr;
    static cudaEvent_t ev0 = nullptr, evA1 = nullptr, evB1 = nullptr,
                       evCSR = nullptr, evA2 = nullptr, evB2 = nullptr;
    if (!sA) {
        cudaStreamCreateWithFlags(&sA, cudaStreamNonBlocking);
        cudaStreamCreateWithFlags(&sB, cudaStreamNonBlocking);
        cudaEventCreateWithFlags(&ev0,   cudaEventDisableTiming);
        cudaEventCreateWithFlags(&evA1,  cudaEventDisableTiming);
        cudaEventCreateWithFlags(&evB1,  cudaEventDisableTiming);
        cudaEventCreateWithFlags(&evCSR, cudaEventDisableTiming);
        cudaEventCreateWithFlags(&evA2,  cudaEventDisableTiming);
        cudaEventCreateWithFlags(&evB2,  cudaEventDisableTiming);
    }

    int nbN = (N + 255) / 256;
    int nbE = (ET + 255) / 256;
    int nbW = (N * 32 + 255) / 256;

    int mtiles = (N + 15) / 16;
    int gx = (mtiles + 3) / 4;           // GEMM grid (y = 1 now)
    int atotal = gx * 4 * 16 * 32;       // A-pack threads
    int apb = (atotal + 255) / 256;

    // ---- fork ----
    cudaEventRecord(ev0, 0);
    cudaStreamWaitEvent(sA, ev0, 0);
    cudaStreamWaitEvent(sB, ev0, 0);

    // branch A: edge dtype + CSR build
    detect_mode<<<1, 256, 0, sA>>>(ei, in_sizes[1], N);
    zero_counts<<<nbN, 256, 0, sA>>>(N);
    count_deg<<<nbE, 256, 0, sA>>>(ei, E, N);
    block_sums<<<nbN, 256, 0, sA>>>(N);
    scan_bsums<<<1, 256, 0, sA>>>(nbN, N);
    write_rows<<<nbN, 256, 0, sA>>>(N);
    scatter_edges<<<nbE, 256, 0, sA>>>(ei, E, N);
    cudaEventRecord(evCSR, sA);

    // branch B: weight fragments, then xr-GEMM layer 1 (after A-pack ready)
    prepack_B<<<128, 256, 0, sB>>>(Wl1, Wr1, Wl2, Wr2);

    // main stream: A-pack layer 1, xl-GEMM
    prepack_A<<<apb, 256>>>(x, N, atotal);
    cudaEventRecord(evA1, 0);
    cudaStreamWaitEvent(sB, evA1, 0);
    gemm_mma<<<gx, 256, 0, sB>>>(bph + 1 * 8192, bpl + 1 * 8192, xr, N);
    cudaEventRecord(evB1, sB);
    gemm_mma<<<gx, 256>>>(bph + 0 * 8192, bpl + 0 * 8192, xl, N);

    // join: fused edge layer 1 needs xl, xr, CSR
    cudaStreamWaitEvent(0, evB1, 0);
    cudaStreamWaitEvent(0, evCSR, 0);
    dst_fused<4, 0><<<nbW, 256>>>(xl, xr, att1, b1, hb, N);

    // layer 2
    prepack_A<<<apb, 256>>>(hb, N, atotal);
    cudaEventRecord(evA2, 0);
    cudaStreamWaitEvent(sB, evA2, 0);
    gemm_mma<<<gx, 256, 0, sB>>>(bph + 3 * 8192, bpl + 3 * 8192, xr, N);
    cudaEventRecord(evB2, sB);
    gemm_mma<<<gx, 256>>>(bph + 2 * 8192, bpl + 2 * 8192, xl, N);

    cudaStreamWaitEvent(0, evB2, 0);
    dst_fused<1, 1><<<nbW, 256>>>(xl, xr, att2, b2, out, N);
}